// round 3
// baseline (speedup 1.0000x reference)
#include <cuda_runtime.h>

// 5x5 median filter, reflect padding, [16,3,256,256] fp32.
//
// Per thread: 4 horizontally-adjacent output pixels.
//  - sort 8 shared columns (9-CAS sort5, arithmetic CAS on FMA pipe)
//  - per pixel: rank-row SET selection (top2/top3/mid3/bot3/bot2);
//    mid3 network also on FMA pipe; rest on ALU (FMNMX)
//  - forgetful selection of rank-7-of-13 with tree minmax (ALU)
// Dual-pipe balance: ~536 alu ops + ~480 fma ops per thread vs 728 alu before.

#define BX 16
#define BY 16
#define PPT 4
#define OUT_W (BX * PPT)        // 64
#define OUT_H BY                // 16
#define PAD 2
#define TILE_W (OUT_W + 2*PAD)  // 68
#define TILE_H (OUT_H + 2*PAD)  // 20
#define IMG 256

// ALU-pipe CAS (2x FMNMX).
__device__ __forceinline__ void cas(float& a, float& b) {
    float lo = fminf(a, b);
    float hi = fmaxf(a, b);
    a = lo;
    b = hi;
}

// FMA-pipe CAS: min/max via sum/absdiff arithmetic (FADD/FMUL only).
// Exact to ~1 ulp; inputs are in [0,1) so no overflow/cancellation hazards.
__device__ __forceinline__ void cas_fma(float& a, float& b) {
    float d = a - b;
    float s = a + b;
    float ad = fabsf(d);
    float lo = (s - ad) * 0.5f;
    float hi = lo + ad;
    a = lo;
    b = hi;
}

// Optimal 9-CAS sorting network for 5 elements, on the FMA pipe.
__device__ __forceinline__ void sort5_fma(float& a, float& b, float& c, float& d, float& e) {
    cas_fma(a, b); cas_fma(d, e); cas_fma(c, e); cas_fma(c, d); cas_fma(b, e);
    cas_fma(a, d); cas_fma(a, c); cas_fma(b, d); cas_fma(b, c);
}

__device__ __forceinline__ int reflect_idx(int i, int n) {
    i = (i < 0) ? -i : i;
    i = (i >= n) ? (2 * n - 2 - i) : i;
    return i;
}

__global__ __launch_bounds__(BX * BY, 3) void median5_kernel(
    const float* __restrict__ in, float* __restrict__ out) {
    __shared__ float tile[TILE_H][TILE_W];

    const int plane = blockIdx.z;  // 48 planes
    const float* src = in + (size_t)plane * IMG * IMG;
    float* dst = out + (size_t)plane * IMG * IMG;

    const int bx = blockIdx.x * OUT_W;
    const int by = blockIdx.y * OUT_H;
    const int tid = threadIdx.y * BX + threadIdx.x;

    // Cooperative halo tile load with reflect padding.
    #pragma unroll
    for (int i = tid; i < TILE_H * TILE_W; i += BX * BY) {
        int r = i / TILE_W;
        int c = i - r * TILE_W;
        int gy = reflect_idx(by + r - PAD, IMG);
        int gx = reflect_idx(bx + c - PAD, IMG);
        tile[r][c] = src[gy * IMG + gx];
    }
    __syncthreads();

    // Load 8 columns x 5 rows via two float4 loads per row.
    float col[8][5];
    #pragma unroll
    for (int r = 0; r < 5; r++) {
        const float4* rp =
            reinterpret_cast<const float4*>(&tile[threadIdx.y + r][threadIdx.x * PPT]);
        float4 lo = rp[0];
        float4 hi = rp[1];
        col[0][r] = lo.x; col[1][r] = lo.y; col[2][r] = lo.z; col[3][r] = lo.w;
        col[4][r] = hi.x; col[5][r] = hi.y; col[6][r] = hi.z; col[7][r] = hi.w;
    }
    #pragma unroll
    for (int j = 0; j < 8; j++)
        sort5_fma(col[j][0], col[j][1], col[j][2], col[j][3], col[j][4]);

    float results[PPT];
    #pragma unroll
    for (int p = 0; p < PPT; p++) {
        float a, b, c, d, e;

        // Row 0 (column minima): need set of 2 largest. (ALU)
        a = col[p][0]; b = col[p+1][0]; c = col[p+2][0]; d = col[p+3][0]; e = col[p+4][0];
        cas(a, b); cas(c, d); cas(b, d); cas(d, e);   // e = max5
        cas(a, b); cas(c, d); cas(b, d);              // d = 2nd max
        float w0 = e, w1 = d;

        // Row 1: need set of 3 largest (remove bottom-2). (ALU)
        a = col[p][1]; b = col[p+1][1]; c = col[p+2][1]; d = col[p+3][1]; e = col[p+4][1];
        cas(a, b); cas(c, d); cas(a, c); cas(a, e);   // a = min5
        cas(b, c); cas(d, e); cas(b, d);              // b = 2nd min
        float w2 = c, w3 = d, w4 = e;

        // Row 2 (column medians): need middle-3 set. (FMA pipe)
        a = col[p][2]; b = col[p+1][2]; c = col[p+2][2]; d = col[p+3][2]; e = col[p+4][2];
        cas_fma(a, b); cas_fma(c, d); cas_fma(a, c);
        cas_fma(b, d); cas_fma(a, e); cas_fma(e, d);
        float w5 = b, w6 = c, w7 = e;                 // a = min5, d = max5

        // Row 3: need set of 3 smallest (remove top-2). (ALU)
        a = col[p][3]; b = col[p+1][3]; c = col[p+2][3]; d = col[p+3][3]; e = col[p+4][3];
        cas(a, b); cas(c, d); cas(b, d); cas(d, e);   // e = max5
        cas(a, b); cas(c, d); cas(b, d);              // d = 2nd max
        float s0 = a, s1 = b, s2 = c;

        // Row 4 (column maxima): need set of 2 smallest. (ALU)
        a = col[p][4]; b = col[p+1][4]; c = col[p+2][4]; d = col[p+3][4]; e = col[p+4][4];
        cas(a, b); cas(c, d); cas(a, c); cas(a, e);   // a = min5
        cas(b, c); cas(d, e); cas(b, d);              // b = 2nd min
        float s3 = a, s4 = b;

        // Forgetful selection: median = rank 7 (1-indexed) of the 13 candidates. (ALU)
        // minmax8 (tree): w0 = min, w7 = max, survivors w1..w6.
        cas(w0, w1); cas(w2, w3); cas(w4, w5); cas(w6, w7);
        cas(w0, w2); cas(w4, w6); cas(w0, w4);
        cas(w1, w3); cas(w5, w7); cas(w3, w7);
        w0 = s0;
        // minmax7: w0 = min, w6 = max, survivors w1..w5.
        cas(w0, w1); cas(w2, w3); cas(w4, w5);
        cas(w0, w2); cas(w4, w6); cas(w0, w4);
        cas(w1, w3); cas(w5, w6); cas(w3, w6);
        w0 = s1;
        // minmax6: w0 = min, w5 = max, survivors w1..w4.
        cas(w0, w1); cas(w2, w3); cas(w4, w5);
        cas(w0, w2); cas(w0, w4);
        cas(w1, w3); cas(w3, w5);
        w0 = s2;
        // minmax5: w0 = min, w3 = max, survivors w1, w2, w4.
        cas(w0, w1); cas(w2, w3); cas(w0, w2); cas(w1, w3); cas(w0, w4); cas(w4, w3);
        w0 = s3;
        // minmax4 on (w0, w1, w2, w4): w0 = min, w4 = max, survivors w1, w2.
        cas(w0, w1); cas(w2, w4); cas(w0, w2); cas(w1, w4);
        w0 = s4;
        // median of 3 -> w1.
        cas(w0, w1); cas(w1, w2); cas(w0, w1);

        results[p] = w1;
    }

    const int gy = by + threadIdx.y;
    float4 r4 = make_float4(results[0], results[1], results[2], results[3]);
    *reinterpret_cast<float4*>(&dst[gy * IMG + bx + threadIdx.x * PPT]) = r4;
}

extern "C" void kernel_launch(void* const* d_in, const int* in_sizes, int n_in,
                              void* d_out, int out_size) {
    const float* image = (const float*)d_in[0];
    float* out = (float*)d_out;
    (void)in_sizes; (void)n_in; (void)out_size;

    dim3 block(BX, BY);
    dim3 grid(IMG / OUT_W, IMG / OUT_H, 16 * 3);
    median5_kernel<<<grid, block>>>(image, out);
}